// round 6
// baseline (speedup 1.0000x reference)
#include <cuda_runtime.h>
#include <math.h>

// Problem constants
#define NB 2
#define T 2048
#define DM 1024
#define NH 16
#define DK 64
#define NT (NB*T)           // 4096 rows

typedef unsigned long long ull;

// ---- packed fp32x2 helpers (sm_100+ PTX) ----------------------------------
__device__ __forceinline__ ull pack2(float lo, float hi) {
    ull r; asm("mov.b64 %0, {%1, %2};" : "=l"(r) : "f"(lo), "f"(hi)); return r;
}
__device__ __forceinline__ ull dup2(float v) { return pack2(v, v); }
__device__ __forceinline__ void unpack2(ull v, float& lo, float& hi) {
    asm("mov.b64 {%0, %1}, %2;" : "=f"(lo), "=f"(hi) : "l"(v));
}
__device__ __forceinline__ void ffma2(ull& d, ull a, ull b) {
    asm("fma.rn.f32x2 %0, %1, %2, %0;" : "+l"(d) : "l"(a), "l"(b));
}
__device__ __forceinline__ ull mul2(ull a, ull b) {
    ull r; asm("mul.rn.f32x2 %0, %1, %2;" : "=l"(r) : "l"(a), "l"(b)); return r;
}

// Scratch (device globals — no allocations allowed)
__device__ float g_Qh[NB*NH*T*DK];
__device__ float g_Kh[NB*NH*T*DK];
__device__ float g_Vh[NB*NH*T*DK];
__device__ float g_A [NT*DM];

// ---------------------------------------------------------------------------
// GEMM: C[M,N] = A[M,K] @ B[K,N] + bias[N]
// mode 0: row-major out. mode 1: head-split scatter out[((b*NH+h)*T+t)*DK+d]
// 128x128 tile, TK=8, 256 threads, 8x8 micro-tile, f32x2 FMA, double-buffered.
// ---------------------------------------------------------------------------
__global__ __launch_bounds__(256) void gemm_kernel(
    const float* __restrict__ A, const float* __restrict__ B,
    const float* __restrict__ bias, float* __restrict__ C,
    int M, int N, int K, int mode)
{
    __shared__ float As[2][8][128];
    __shared__ float Bs[2][8][128];

    int tid = threadIdx.x;
    int bm = blockIdx.y * 128;
    int bn = blockIdx.x * 128;
    int tx = tid & 15;
    int ty = tid >> 4;

    ull acc2[8][4];
#pragma unroll
    for (int i = 0; i < 8; i++)
#pragma unroll
        for (int j = 0; j < 4; j++) acc2[i][j] = 0ULL;

    int a_m = tid >> 1;
    int a_k = (tid & 1) * 4;
    int b_k = tid >> 5;
    int b_n = (tid & 31) * 4;

    const float* Aptr = A + (size_t)(bm + a_m) * K + a_k;
    const float* Bptr = B + (size_t)b_k * N + bn + b_n;

    // preload tile 0
    float4 av = *(const float4*)Aptr;
    float4 bv = *(const float4*)Bptr;
    As[0][a_k + 0][a_m] = av.x;
    As[0][a_k + 1][a_m] = av.y;
    As[0][a_k + 2][a_m] = av.z;
    As[0][a_k + 3][a_m] = av.w;
    *(float4*)&Bs[0][b_k][b_n] = bv;
    __syncthreads();

    int p = 0;
    for (int k0 = 0; k0 < K; k0 += 8) {
        bool more = (k0 + 8 < K);
        if (more) {
            av = *(const float4*)(Aptr + k0 + 8);
            bv = *(const float4*)(Bptr + (size_t)(k0 + 8) * N);
        }
#pragma unroll
        for (int kk = 0; kk < 8; kk++) {
            float a[8];
            *(float4*)&a[0] = *(const float4*)&As[p][kk][ty * 4];
            *(float4*)&a[4] = *(const float4*)&As[p][kk][64 + ty * 4];
            ulonglong2 b01 = *(const ulonglong2*)&Bs[p][kk][tx * 4];
            ulonglong2 b23 = *(const ulonglong2*)&Bs[p][kk][64 + tx * 4];
#pragma unroll
            for (int i = 0; i < 8; i++) {
                ull ad = dup2(a[i]);
                ffma2(acc2[i][0], ad, b01.x);
                ffma2(acc2[i][1], ad, b01.y);
                ffma2(acc2[i][2], ad, b23.x);
                ffma2(acc2[i][3], ad, b23.y);
            }
        }
        if (more) {
            As[p ^ 1][a_k + 0][a_m] = av.x;
            As[p ^ 1][a_k + 1][a_m] = av.y;
            As[p ^ 1][a_k + 2][a_m] = av.z;
            As[p ^ 1][a_k + 3][a_m] = av.w;
            *(float4*)&Bs[p ^ 1][b_k][b_n] = bv;
        }
        __syncthreads();
        p ^= 1;
    }

#pragma unroll
    for (int i = 0; i < 8; i++) {
        int m = bm + ty * 4 + (i & 3) + (i & 4) * 16;
#pragma unroll
        for (int pr = 0; pr < 4; pr++) {
            float lo, hi;
            unpack2(acc2[i][pr], lo, hi);
            int n0 = bn + (pr & 2) * 32 + tx * 4 + (pr & 1) * 2;
            float v0 = lo + bias[n0];
            float v1 = hi + bias[n0 + 1];
            if (mode == 0) {
                C[(size_t)m * N + n0]     = v0;
                C[(size_t)m * N + n0 + 1] = v1;
            } else {
                int bb = m >> 11;
                int t  = m & (T - 1);
                int h0 = n0 >> 6;
                int d0 = n0 & (DK - 1);
                size_t base = (((size_t)(bb * NH + h0)) * T + t) * DK;
                C[base + d0]     = v0;
                C[base + d0 + 1] = v1;   // pair never crosses a head (64-aligned)
            }
        }
    }
}

// ---------------------------------------------------------------------------
// Flash attention: BQ=128 q-rows x BK=128 keys per tile, 512 threads (16 warps).
// Micro-tile: score 4 rows x 8 cols (split-64 col map), PV 4 rows x 4 dcols.
// f32x2 packed FMA throughout.
// ---------------------------------------------------------------------------
#define BQ 128
#define BK 128
#define QST 132
#define VST 68
#define ATHR 512
#define ATTN_SMEM ((2*64*QST + BK*VST + BQ*QST) * 4)

__global__ __launch_bounds__(ATHR, 1) void attn_kernel(
    const float* __restrict__ Qh, const float* __restrict__ Kh,
    const float* __restrict__ Vh, const int* __restrict__ mask,
    float* __restrict__ Aout)
{
    extern __shared__ float sm[];
    float* Qt = sm;                      // [64 d][QST]  (transposed Q)
    float* Kt = Qt + 64 * QST;           // [64 d][QST]  (transposed K)
    float* Vs = Kt + 64 * QST;           // [BK c][VST]
    float* Ps = Vs + BK * VST;           // [BQ r][QST]
    __shared__ float Mk[BK];

    int tid = threadIdx.x;
    int tx = tid & 15;
    int ty = tid >> 4;          // 0..31, 4 rows each
    int q0 = blockIdx.x * BQ;
    int h  = blockIdx.y;
    int b  = blockIdx.z;
    int bh = b * NH + h;

    const float* Qbase = Qh + ((size_t)bh * T + q0) * DK;
    const float* Kbase = Kh + (size_t)bh * T * DK;
    const float* Vbase = Vh + (size_t)bh * T * DK;

    // Load Q tile transposed
    for (int i = tid; i < BQ * 16; i += ATHR) {
        int r  = i >> 4;
        int d4 = (i & 15) * 4;
        float4 qv = *(const float4*)&Qbase[r * DK + d4];
        Qt[(d4 + 0) * QST + r] = qv.x;
        Qt[(d4 + 1) * QST + r] = qv.y;
        Qt[(d4 + 2) * QST + r] = qv.z;
        Qt[(d4 + 3) * QST + r] = qv.w;
    }

    float m_r[4], l_r[4];
    ull acc2[4][2];
#pragma unroll
    for (int i = 0; i < 4; i++) {
        m_r[i] = -1e30f;
        l_r[i] = 0.f;
        acc2[i][0] = 0ULL;
        acc2[i][1] = 0ULL;
    }

    const float scale = 0.125f;   // 1/sqrt(64)

    for (int k0 = 0; k0 < T; k0 += BK) {
        // Load K (transposed) and V tiles + mask
        for (int i = tid; i < BK * 16; i += ATHR) {
            int r  = i >> 4;
            int d4 = (i & 15) * 4;
            float4 kv = *(const float4*)&Kbase[(k0 + r) * DK + d4];
            Kt[(d4 + 0) * QST + r] = kv.x;
            Kt[(d4 + 1) * QST + r] = kv.y;
            Kt[(d4 + 2) * QST + r] = kv.z;
            Kt[(d4 + 3) * QST + r] = kv.w;
            float4 vv = *(const float4*)&Vbase[(k0 + r) * DK + d4];
            *(float4*)&Vs[r * VST + d4] = vv;
        }
        if (tid < BK)
            Mk[tid] = mask[b * T + k0 + tid] ? 0.f : -1e30f;
        __syncthreads();

        // Score phase: 4 rows (ty*4+i) x 8 cols (tx*4+{0..3}, 64+tx*4+{0..3})
        ull s2[4][4];
#pragma unroll
        for (int i = 0; i < 4; i++)
#pragma unroll
            for (int j = 0; j < 4; j++) s2[i][j] = 0ULL;

#pragma unroll 4
        for (int d = 0; d < DK; d++) {
            float4 a = *(const float4*)&Qt[d * QST + ty * 4];
            ulonglong2 b01 = *(const ulonglong2*)&Kt[d * QST + tx * 4];
            ulonglong2 b23 = *(const ulonglong2*)&Kt[d * QST + 64 + tx * 4];
            ull ad;
            ad = dup2(a.x);
            ffma2(s2[0][0], ad, b01.x); ffma2(s2[0][1], ad, b01.y);
            ffma2(s2[0][2], ad, b23.x); ffma2(s2[0][3], ad, b23.y);
            ad = dup2(a.y);
            ffma2(s2[1][0], ad, b01.x); ffma2(s2[1][1], ad, b01.y);
            ffma2(s2[1][2], ad, b23.x); ffma2(s2[1][3], ad, b23.y);
            ad = dup2(a.z);
            ffma2(s2[2][0], ad, b01.x); ffma2(s2[2][1], ad, b01.y);
            ffma2(s2[2][2], ad, b23.x); ffma2(s2[2][3], ad, b23.y);
            ad = dup2(a.w);
            ffma2(s2[3][0], ad, b01.x); ffma2(s2[3][1], ad, b01.y);
            ffma2(s2[3][2], ad, b23.x); ffma2(s2[3][3], ad, b23.y);
        }

        float mk[8];
#pragma unroll
        for (int j = 0; j < 4; j++) {
            mk[j]     = Mk[tx * 4 + j];
            mk[4 + j] = Mk[64 + tx * 4 + j];
        }

        // Online softmax (rows reduced across the 16 tx lanes)
#pragma unroll
        for (int i = 0; i < 4; i++) {
            float sc[8];
            unpack2(s2[i][0], sc[0], sc[1]);
            unpack2(s2[i][1], sc[2], sc[3]);
            unpack2(s2[i][2], sc[4], sc[5]);
            unpack2(s2[i][3], sc[6], sc[7]);
#pragma unroll
            for (int j = 0; j < 8; j++) sc[j] = sc[j] * scale + mk[j];

            float mx = sc[0];
#pragma unroll
            for (int j = 1; j < 8; j++) mx = fmaxf(mx, sc[j]);
#pragma unroll
            for (int msk = 8; msk >= 1; msk >>= 1)
                mx = fmaxf(mx, __shfl_xor_sync(0xffffffffu, mx, msk));
            float m_new = fmaxf(m_r[i], mx);

            float pj[8];
            float sum = 0.f;
#pragma unroll
            for (int j = 0; j < 8; j++) { pj[j] = __expf(sc[j] - m_new); sum += pj[j]; }
#pragma unroll
            for (int msk = 8; msk >= 1; msk >>= 1)
                sum += __shfl_xor_sync(0xffffffffu, sum, msk);

            float alpha = __expf(m_r[i] - m_new);
            l_r[i] = l_r[i] * alpha + sum;
            m_r[i] = m_new;
            ull am = dup2(alpha);
            acc2[i][0] = mul2(acc2[i][0], am);
            acc2[i][1] = mul2(acc2[i][1], am);

            int r = ty * 4 + i;
            *(float4*)&Ps[r * QST + tx * 4]      = make_float4(pj[0], pj[1], pj[2], pj[3]);
            *(float4*)&Ps[r * QST + 64 + tx * 4] = make_float4(pj[4], pj[5], pj[6], pj[7]);
        }
        __syncthreads();

        // PV phase: acc[4 rows][4 dcols = tx*4..tx*4+3]
#pragma unroll 2
        for (int c0 = 0; c0 < BK; c0 += 4) {
            ulonglong2 v0 = *(const ulonglong2*)&Vs[(c0 + 0) * VST + tx * 4];
            ulonglong2 v1 = *(const ulonglong2*)&Vs[(c0 + 1) * VST + tx * 4];
            ulonglong2 v2 = *(const ulonglong2*)&Vs[(c0 + 2) * VST + tx * 4];
            ulonglong2 v3 = *(const ulonglong2*)&Vs[(c0 + 3) * VST + tx * 4];
#pragma unroll
            for (int i = 0; i < 4; i++) {
                float4 pv = *(const float4*)&Ps[(ty * 4 + i) * QST + c0];
                ull pd;
                pd = dup2(pv.x); ffma2(acc2[i][0], pd, v0.x); ffma2(acc2[i][1], pd, v0.y);
                pd = dup2(pv.y); ffma2(acc2[i][0], pd, v1.x); ffma2(acc2[i][1], pd, v1.y);
                pd = dup2(pv.z); ffma2(acc2[i][0], pd, v2.x); ffma2(acc2[i][1], pd, v2.y);
                pd = dup2(pv.w); ffma2(acc2[i][0], pd, v3.x); ffma2(acc2[i][1], pd, v3.y);
            }
        }
        __syncthreads();
    }

    // Write A in [N*T, DM] layout
#pragma unroll
    for (int i = 0; i < 4; i++) {
        float inv = 1.f / l_r[i];
        float o0, o1, o2, o3;
        unpack2(acc2[i][0], o0, o1);
        unpack2(acc2[i][1], o2, o3);
        int t = q0 + ty * 4 + i;
        float4 o = make_float4(o0 * inv, o1 * inv, o2 * inv, o3 * inv);
        *(float4*)&Aout[((size_t)(b * T + t)) * DM + h * DK + tx * 4] = o;
    }
}

// ---------------------------------------------------------------------------
extern "C" void kernel_launch(void* const* d_in, const int* in_sizes, int n_in,
                              void* d_out, int out_size)
{
    const float* q   = (const float*)d_in[0];
    const float* k   = (const float*)d_in[1];
    const float* v   = (const float*)d_in[2];
    const int*   msk = (const int*)  d_in[3];
    const float* Wq  = (const float*)d_in[4];
    const float* bq  = (const float*)d_in[5];
    const float* Wk  = (const float*)d_in[6];
    const float* bk  = (const float*)d_in[7];
    const float* Wv  = (const float*)d_in[8];
    const float* bv  = (const float*)d_in[9];
    const float* Wo  = (const float*)d_in[10];
    const float* bo  = (const float*)d_in[11];
    float* out = (float*)d_out;

    float* Qh;   cudaGetSymbolAddress((void**)&Qh, g_Qh);
    float* Kh;   cudaGetSymbolAddress((void**)&Kh, g_Kh);
    float* Vh;   cudaGetSymbolAddress((void**)&Vh, g_Vh);
    float* Abuf; cudaGetSymbolAddress((void**)&Abuf, g_A);

    cudaFuncSetAttribute(attn_kernel,
                         cudaFuncAttributeMaxDynamicSharedMemorySize, ATTN_SMEM);

    dim3 gg(DM / 128, NT / 128);   // (8, 32)
    gemm_kernel<<<gg, 256>>>(q, Wq, bq, Qh, NT, DM, DM, 1);
    gemm_kernel<<<gg, 256>>>(k, Wk, bk, Kh, NT, DM, DM, 1);
    gemm_kernel<<<gg, 256>>>(v, Wv, bv, Vh, NT, DM, DM, 1);

    dim3 ga(T / BQ, NH, NB);       // (16, 16, 2)
    attn_kernel<<<ga, ATHR, ATTN_SMEM>>>(Qh, Kh, Vh, msk, Abuf);

    gemm_kernel<<<gg, 256>>>(Abuf, Wo, bo, out, NT, DM, DM, 0);
}

// round 11
// speedup vs baseline: 1.2210x; 1.2210x over previous
#include <cuda_runtime.h>
#include <cuda_bf16.h>
#include <cstdint>
#include <math.h>

// Problem constants
#define NB 2
#define T 2048
#define DM 1024
#define NH 16
#define DK 64
#define NT (NB*T)           // 4096 rows

// ---- bf16 split helpers ----------------------------------------------------
__device__ __forceinline__ uint32_t packbf(float lo, float hi) {
    uint32_t r;
    asm("cvt.rn.bf16x2.f32 %0, %1, %2;" : "=r"(r) : "f"(hi), "f"(lo));
    return r;
}
// x -> element0 (low 16), y -> element1 (high 16); h + l reconstruct (x,y)
__device__ __forceinline__ void split2(float x, float y, uint32_t& h, uint32_t& l) {
    h = packbf(x, y);
    float hx = __uint_as_float(h << 16);
    float hy = __uint_as_float(h & 0xffff0000u);
    l = packbf(x - hx, y - hy);
}

// mma.sync m16n8k16 bf16 -> f32, D += A*B
#define MMA16816(d, a0, a1, a2, a3, b0, b1)                                    \
    asm volatile(                                                              \
        "mma.sync.aligned.m16n8k16.row.col.f32.bf16.bf16.f32 "                 \
        "{%0,%1,%2,%3}, {%4,%5,%6,%7}, {%8,%9}, {%0,%1,%2,%3};"                \
        : "+f"((d)[0]), "+f"((d)[1]), "+f"((d)[2]), "+f"((d)[3])               \
        : "r"(a0), "r"(a1), "r"(a2), "r"(a3), "r"(b0), "r"(b1))

// Scratch (device globals — no allocations allowed)
// Q/K split pairs: [b*NH+h][t][d] as b32 (d-pairs). V: [b*NH+h][d][t] (t-pairs).
__device__ uint32_t g_Qhi[NB*NH*T*(DK/2)], g_Qlo[NB*NH*T*(DK/2)];
__device__ uint32_t g_Khi[NB*NH*T*(DK/2)], g_Klo[NB*NH*T*(DK/2)];
__device__ uint32_t g_Vhi[NB*NH*DK*(T/2)], g_Vlo[NB*NH*DK*(T/2)];
__device__ float    g_A  [NT*DM];

// ===========================================================================
// GEMM via mma.sync bf16-split: C[4096,1024] = A @ B + bias
// Tile 128x128, 8 warps (warp grid 4m x 2n, 32x64 per warp), k-chunks of 32.
// mode 0: f32 row-major out.
// mode 1: bf16 hi/lo head-split pairs (for Q, K).
// mode 2: bf16 hi/lo transposed [bh][d][t] pairs via smem (for V).
// ===========================================================================
#define GSTR 20                        // b32 row stride (20 mod 32 -> conflict-free frags)
#define GT_TILE_B (128 * GSTR * 4)     // 10240 bytes per tile
#define GCHUNK_B  (4 * GT_TILE_B)      // Ah, Al, Bh, Bl
#define GEMM_SMEM (2 * GCHUNK_B)       // 81920 (also covers 128x129 f32 Csm = 66048)

__device__ __forceinline__ void g_load_regs(
    const float* __restrict__ A, const float* __restrict__ B,
    int bm, int bn, int c, float4 ar[4], float4 br[4])
{
    int tid = threadIdx.x;
#pragma unroll
    for (int j = 0; j < 4; j++) {
        int idx = tid + j * 256;            // 0..1023
        int arow = idx >> 3, kf = idx & 7;  // A: 128 rows x 8 float4
        ar[j] = *(const float4*)&A[(size_t)(bm + arow) * DM + c * 32 + kf * 4];
        int kk = idx >> 5, n4 = idx & 31;   // B: 32 k x 32 float4
        br[j] = *(const float4*)&B[(size_t)(c * 32 + kk) * DM + bn + n4 * 4];
    }
}

__device__ __forceinline__ void g_store_smem(char* buf, const float4 ar[4], const float4 br[4])
{
    uint32_t* Ah = (uint32_t*)buf;
    uint32_t* Al = (uint32_t*)(buf + GT_TILE_B);
    __nv_bfloat16* Bh = (__nv_bfloat16*)(buf + 2 * GT_TILE_B);
    __nv_bfloat16* Bl = (__nv_bfloat16*)(buf + 3 * GT_TILE_B);
    int tid = threadIdx.x;
#pragma unroll
    for (int j = 0; j < 4; j++) {
        int idx = tid + j * 256;
        int arow = idx >> 3, kf = idx & 7;
        uint32_t h0, l0, h1, l1;
        split2(ar[j].x, ar[j].y, h0, l0);
        split2(ar[j].z, ar[j].w, h1, l1);
        Ah[arow * GSTR + kf * 2]     = h0;
        Ah[arow * GSTR + kf * 2 + 1] = h1;
        Al[arow * GSTR + kf * 2]     = l0;
        Al[arow * GSTR + kf * 2 + 1] = l1;

        int kk = idx >> 5, n4 = idx & 31;
        float v[4] = {br[j].x, br[j].y, br[j].z, br[j].w};
#pragma unroll
        for (int m = 0; m < 4; m++) {
            int n = n4 * 4 + m;
            __nv_bfloat16 bh = __float2bfloat16(v[m]);
            __nv_bfloat16 bl = __float2bfloat16(v[m] - __bfloat162float(bh));
            Bh[n * (GSTR * 2) + kk] = bh;
            Bl[n * (GSTR * 2) + kk] = bl;
        }
    }
}

__global__ __launch_bounds__(256, 1) void gemm_mma(
    const float* __restrict__ A, const float* __restrict__ B,
    const float* __restrict__ bias, float* __restrict__ C,
    uint32_t* __restrict__ Chi, uint32_t* __restrict__ Clo, int mode)
{
    extern __shared__ char sb[];
    int tid = threadIdx.x;
    int wid = tid >> 5, lane = tid & 31;
    int lq = lane >> 2, lr = lane & 3;
    int wm = wid & 3, wn = wid >> 2;
    int bn = blockIdx.x * 128;
    int bm = blockIdx.y * 128;

    float acc[2][8][4];
#pragma unroll
    for (int mt = 0; mt < 2; mt++)
#pragma unroll
        for (int nt = 0; nt < 8; nt++)
#pragma unroll
            for (int i = 0; i < 4; i++) acc[mt][nt][i] = 0.f;

    {
        float4 ar[4], br[4];
        g_load_regs(A, B, bm, bn, 0, ar, br);
        g_store_smem(sb, ar, br);
    }
    __syncthreads();

    for (int c = 0; c < 32; c++) {
        int p = c & 1;
        float4 ar[4], br[4];
        bool more = (c + 1 < 32);
        if (more) g_load_regs(A, B, bm, bn, c + 1, ar, br);

        char* buf = sb + p * GCHUNK_B;
        const uint32_t* Ah32 = (const uint32_t*)buf;
        const uint32_t* Al32 = (const uint32_t*)(buf + GT_TILE_B);
        const uint32_t* Bh32 = (const uint32_t*)(buf + 2 * GT_TILE_B);
        const uint32_t* Bl32 = (const uint32_t*)(buf + 3 * GT_TILE_B);

#pragma unroll
        for (int s = 0; s < 2; s++) {
            int ka = s * 8 + lr;
            uint32_t ah[2][4], al[2][4];
#pragma unroll
            for (int mt = 0; mt < 2; mt++) {
                int r = wm * 32 + mt * 16 + lq;
                ah[mt][0] = Ah32[r * GSTR + ka];
                ah[mt][1] = Ah32[(r + 8) * GSTR + ka];
                ah[mt][2] = Ah32[r * GSTR + ka + 4];
                ah[mt][3] = Ah32[(r + 8) * GSTR + ka + 4];
                al[mt][0] = Al32[r * GSTR + ka];
                al[mt][1] = Al32[(r + 8) * GSTR + ka];
                al[mt][2] = Al32[r * GSTR + ka + 4];
                al[mt][3] = Al32[(r + 8) * GSTR + ka + 4];
            }
#pragma unroll
            for (int nt = 0; nt < 8; nt++) {
                int rn = wn * 64 + nt * 8 + lq;
                uint32_t bh0 = Bh32[rn * GSTR + ka];
                uint32_t bh1 = Bh32[rn * GSTR + ka + 4];
                uint32_t bl0 = Bl32[rn * GSTR + ka];
                uint32_t bl1 = Bl32[rn * GSTR + ka + 4];
#pragma unroll
                for (int mt = 0; mt < 2; mt++) {
                    MMA16816(acc[mt][nt], ah[mt][0], ah[mt][1], ah[mt][2], ah[mt][3], bh0, bh1);
                    MMA16816(acc[mt][nt], ah[mt][0], ah[mt][1], ah[mt][2], ah[mt][3], bl0, bl1);
                    MMA16816(acc[mt][nt], al[mt][0], al[mt][1], al[mt][2], al[mt][3], bh0, bh1);
                }
            }
        }
        if (more) g_store_smem(sb + (p ^ 1) * GCHUNK_B, ar, br);
        __syncthreads();
    }

    // ---- epilogue ----
    if (mode == 0) {
#pragma unroll
        for (int mt = 0; mt < 2; mt++)
#pragma unroll
            for (int nt = 0; nt < 8; nt++) {
                int m = bm + wm * 32 + mt * 16 + lq;
                int n = bn + wn * 64 + nt * 8 + lr * 2;
                float b0 = bias[n], b1 = bias[n + 1];
                float2 v0 = make_float2(acc[mt][nt][0] + b0, acc[mt][nt][1] + b1);
                float2 v1 = make_float2(acc[mt][nt][2] + b0, acc[mt][nt][3] + b1);
                *(float2*)&C[(size_t)m * DM + n] = v0;
                *(float2*)&C[(size_t)(m + 8) * DM + n] = v1;
            }
    } else if (mode == 1) {
#pragma unroll
        for (int mt = 0; mt < 2; mt++)
#pragma unroll
            for (int nt = 0; nt < 8; nt++) {
                int m = bm + wm * 32 + mt * 16 + lq;
                int n = bn + wn * 64 + nt * 8 + lr * 2;
                float b0 = bias[n], b1 = bias[n + 1];
                int hh = n >> 6, d = n & (DK - 1);
#pragma unroll
                for (int rr = 0; rr < 2; rr++) {
                    int mm = m + rr * 8;
                    int bb = mm >> 11, t = mm & (T - 1);
                    float v0 = acc[mt][nt][rr * 2 + 0] + b0;
                    float v1 = acc[mt][nt][rr * 2 + 1] + b1;
                    uint32_t h, l;
                    split2(v0, v1, h, l);
                    size_t o = ((size_t)(bb * NH + hh) * T + t) * (DK / 2) + (d >> 1);
                    Chi[o] = h;
                    Clo[o] = l;
                }
            }
    } else {
        // mode 2: stage into smem, write transposed bf16 pairs [bh][d][t]
        float* Csm = (float*)sb;   // [128][129]
#pragma unroll
        for (int mt = 0; mt < 2; mt++)
#pragma unroll
            for (int nt = 0; nt < 8; nt++) {
                int ml = wm * 32 + mt * 16 + lq;
                int nl = wn * 64 + nt * 8 + lr * 2;
                float b0 = bias[bn + nl], b1 = bias[bn + nl + 1];
                Csm[ml * 129 + nl]       = acc[mt][nt][0] + b0;
                Csm[ml * 129 + nl + 1]   = acc[mt][nt][1] + b1;
                Csm[(ml + 8) * 129 + nl]     = acc[mt][nt][2] + b0;
                Csm[(ml + 8) * 129 + nl + 1] = acc[mt][nt][3] + b1;
            }
        __syncthreads();
        int bb = bm >> 11;
        int tbase = (bm & (T - 1)) >> 1;
        for (int idx = tid; idx < 128 * 64; idx += 256) {
            int nl = idx >> 6;         // 0..127 (d within 2 heads)
            int tp = idx & 63;         // t-pair
            float v0 = Csm[(tp * 2) * 129 + nl];
            float v1 = Csm[(tp * 2 + 1) * 129 + nl];
            uint32_t h, l;
            split2(v0, v1, h, l);
            int n = bn + nl;
            int hh = n >> 6, d = n & (DK - 1);
            size_t o = ((size_t)(bb * NH + hh) * DK + d) * (T / 2) + tbase + tp;
            Chi[o] = h;
            Clo[o] = l;
        }
    }
}

// ===========================================================================
// Flash attention via mma.sync bf16-split.
// 256 threads, 8 warps; warp w owns q-rows w*16..w*16+15, all 128 keys.
// S accumulators double as A-fragments for PV (register-resident P).
// ===========================================================================
#define QSTR 36      // b32 row stride for Q/K smem tiles (36 mod 32 = 4)
#define VSTR 68      // b32 row stride for V_t smem tiles  (68 mod 32 = 4)
#define SM_QH 0
#define SM_QL (SM_QH + 128*QSTR*4)
#define SM_KH (SM_QL + 128*QSTR*4)
#define SM_KL (SM_KH + 128*QSTR*4)
#define SM_VH (SM_KL + 128*QSTR*4)
#define SM_VL (SM_VH + 64*VSTR*4)
#define SM_MK (SM_VL + 64*VSTR*4)
#define ATTN_SMEM (SM_MK + 128*4)

__global__ __launch_bounds__(256, 1) void attn_mma(
    const uint32_t* __restrict__ Qhi, const uint32_t* __restrict__ Qlo,
    const uint32_t* __restrict__ Khi, const uint32_t* __restrict__ Klo,
    const uint32_t* __restrict__ Vhi, const uint32_t* __restrict__ Vlo,
    const int* __restrict__ mask, float* __restrict__ Aout)
{
    extern __shared__ char sb[];
    uint32_t* Qh32 = (uint32_t*)(sb + SM_QH);
    uint32_t* Ql32 = (uint32_t*)(sb + SM_QL);
    uint32_t* Kh32 = (uint32_t*)(sb + SM_KH);
    uint32_t* Kl32 = (uint32_t*)(sb + SM_KL);
    uint32_t* Vh32 = (uint32_t*)(sb + SM_VH);
    uint32_t* Vl32 = (uint32_t*)(sb + SM_VL);
    float*    Mk   = (float*)   (sb + SM_MK);

    int tid = threadIdx.x;
    int wid = tid >> 5, lane = tid & 31;
    int lq = lane >> 2, lr = lane & 3;
    int m0 = wid * 16;
    int q0 = blockIdx.x * 128;
    int h  = blockIdx.y;
    int b  = blockIdx.z;
    int bh = b * NH + h;

    // Load Q tile (bf16 pairs) into smem
    {
        const uint32_t* qh = Qhi + ((size_t)bh * T + q0) * (DK / 2);
        const uint32_t* ql = Qlo + ((size_t)bh * T + q0) * (DK / 2);
        for (int idx = tid; idx < 128 * 32; idx += 256) {
            int r = idx >> 5, cc = idx & 31;
            Qh32[r * QSTR + cc] = qh[r * 32 + cc];
            Ql32[r * QSTR + cc] = ql[r * 32 + cc];
        }
    }

    float m_r0 = -1e30f, m_r1 = -1e30f, l_0 = 0.f, l_1 = 0.f;
    float oacc[8][4];
#pragma unroll
    for (int nt = 0; nt < 8; nt++)
#pragma unroll
        for (int i = 0; i < 4; i++) oacc[nt][i] = 0.f;

    const float scale = 0.125f;   // 1/sqrt(64)

    for (int k0 = 0; k0 < T; k0 += 128) {
        __syncthreads();  // protect K/V smem reuse
        {
            const uint32_t* kh = Khi + ((size_t)bh * T + k0) * (DK / 2);
            const uint32_t* kl = Klo + ((size_t)bh * T + k0) * (DK / 2);
            for (int idx = tid; idx < 128 * 32; idx += 256) {
                int r = idx >> 5, cc = idx & 31;
                Kh32[r * QSTR + cc] = kh[r * 32 + cc];
                Kl32[r * QSTR + cc] = kl[r * 32 + cc];
            }
            const uint32_t* vh = Vhi + (size_t)bh * DK * (T / 2) + (k0 >> 1);
            const uint32_t* vl = Vlo + (size_t)bh * DK * (T / 2) + (k0 >> 1);
            for (int idx = tid; idx < 64 * 64; idx += 256) {
                int d = idx >> 6, j = idx & 63;
                Vh32[d * VSTR + j] = vh[(size_t)d * (T / 2) + j];
                Vl32[d * VSTR + j] = vl[(size_t)d * (T / 2) + j];
            }
            if (tid < 128)
                Mk[tid] = mask[b * T + k0 + tid] ? 0.f : -1e30f;
        }
        __syncthreads();

        // ---- score: S = Q K^T ----
        float sacc[16][4];
#pragma unroll
        for (int nt = 0; nt < 16; nt++)
#pragma unroll
            for (int i = 0; i < 4; i++) sacc[nt][i] = 0.f;

#pragma unroll
        for (int s = 0; s < 4; s++) {
            int ka = s * 8 + lr;
            int r = m0 + lq;
            uint32_t ah0 = Qh32[r * QSTR + ka],       ah1 = Qh32[(r + 8) * QSTR + ka];
            uint32_t ah2 = Qh32[r * QSTR + ka + 4],   ah3 = Qh32[(r + 8) * QSTR + ka + 4];
            uint32_t al0 = Ql32[r * QSTR + ka],       al1 = Ql32[(r + 8) * QSTR + ka];
            uint32_t al2 = Ql32[r * QSTR + ka + 4],   al3 = Ql32[(r + 8) * QSTR + ka + 4];
#pragma unroll
            for (int nt = 0; nt < 16; nt++) {
                int rn = nt * 8 + lq;
                uint32_t bh0 = Kh32[rn * QSTR + ka];
                uint32_t bh1 = Kh32[rn * QSTR + ka + 4];
                uint32_t bl0 = Kl32[rn * QSTR + ka];
                uint32_t bl1 = Kl32[rn * QSTR + ka + 4];
                MMA16816(sacc[nt], ah0, ah1, ah2, ah3, bh0, bh1);
                MMA16816(sacc[nt], ah0, ah1, ah2, ah3, bl0, bl1);
                MMA16816(sacc[nt], al0, al1, al2, al3, bh0, bh1);
            }
        }

        // ---- online softmax (rows r0 = m0+lq, r1 = r0+8) ----
        float mx0 = -1e30f, mx1 = -1e30f;
#pragma unroll
        for (int nt = 0; nt < 16; nt++) {
            int cc = nt * 8 + lr * 2;
            float k0m = Mk[cc], k1m = Mk[cc + 1];
            float s0 = sacc[nt][0] * scale + k0m;
            float s1 = sacc[nt][1] * scale + k1m;
            float s2 = sacc[nt][2] * scale + k0m;
            float s3 = sacc[nt][3] * scale + k1m;
            sacc[nt][0] = s0; sacc[nt][1] = s1; sacc[nt][2] = s2; sacc[nt][3] = s3;
            mx0 = fmaxf(mx0, fmaxf(s0, s1));
            mx1 = fmaxf(mx1, fmaxf(s2, s3));
        }
        mx0 = fmaxf(mx0, __shfl_xor_sync(0xffffffffu, mx0, 1));
        mx0 = fmaxf(mx0, __shfl_xor_sync(0xffffffffu, mx0, 2));
        mx1 = fmaxf(mx1, __shfl_xor_sync(0xffffffffu, mx1, 1));
        mx1 = fmaxf(mx1, __shfl_xor_sync(0xffffffffu, mx1, 2));
        float m_new0 = fmaxf(m_r0, mx0);
        float m_new1 = fmaxf(m_r1, mx1);

        float sum0 = 0.f, sum1 = 0.f;
#pragma unroll
        for (int nt = 0; nt < 16; nt++) {
            float p0 = __expf(sacc[nt][0] - m_new0);
            float p1 = __expf(sacc[nt][1] - m_new0);
            float p2 = __expf(sacc[nt][2] - m_new1);
            float p3 = __expf(sacc[nt][3] - m_new1);
            sacc[nt][0] = p0; sacc[nt][1] = p1; sacc[nt][2] = p2; sacc[nt][3] = p3;
            sum0 += p0 + p1;
            sum1 += p2 + p3;
        }
        sum0 += __shfl_xor_sync(0xffffffffu, sum0, 1);
        sum0 += __shfl_xor_sync(0xffffffffu, sum0, 2);
        sum1 += __shfl_xor_sync(0xffffffffu, sum1, 1);
        sum1 += __shfl_xor_sync(0xffffffffu, sum1, 2);

        float alpha0 = __expf(m_r0 - m_new0);
        float alpha1 = __expf(m_r1 - m_new1);
        l_0 = l_0 * alpha0 + sum0;
        l_1 = l_1 * alpha1 + sum1;
        m_r0 = m_new0;
        m_r1 = m_new1;
#pragma unroll
        for (int nt = 0; nt < 8; nt++) {
            oacc[nt][0] *= alpha0; oacc[nt][1] *= alpha0;
            oacc[nt][2] *= alpha1; oacc[nt][3] *= alpha1;
        }

        // ---- PV: O += P V (P from registers) ----
#pragma unroll
        for (int kt = 0; kt < 8; kt++) {
            uint32_t pah[4], pal[4];
            split2(sacc[2 * kt][0],     sacc[2 * kt][1],     pah[0], pal[0]);
            split2(sacc[2 * kt][2],     sacc[2 * kt][3],     pah[1], pal[1]);
            split2(sacc[2 * kt + 1][0], sacc[2 * kt + 1][1], pah[2], pal[2]);
            split2(sacc[2 * kt + 1][2], sacc[2 * kt + 1][3], pah[3], pal[3]);
#pragma unroll
            for (int nt = 0; nt < 8; nt++) {
                int rn = nt * 8 + lq;
                uint32_t vh0 = Vh32[rn * VSTR + kt * 8 + lr];
                uint32_t vh1 = Vh32[rn * VSTR + kt * 8 + lr + 4];
                uint32_t vl0 = Vl32[rn * VSTR + kt * 8 + lr];
                uint32_t vl1 = Vl32[rn * VSTR + kt * 8 + lr + 4];
                MMA16816(oacc[nt], pah[0], pah[1], pah[2], pah[3], vh0, vh1);
                MMA16816(oacc[nt], pah[0], pah[1], pah[2], pah[3], vl0, vl1);
                MMA16816(oacc[nt], pal[0], pal[1], pal[2], pal[3], vh0, vh1);
            }
        }
    }

    // ---- write A [N*T][DM] ----
    float inv0 = 1.f / l_0, inv1 = 1.f / l_1;
    int row0 = q0 + m0 + lq;
#pragma unroll
    for (int nt = 0; nt < 8; nt++) {
        int d = h * DK + nt * 8 + lr * 2;
        *(float2*)&Aout[(size_t)(b * T + row0) * DM + d] =
            make_float2(oacc[nt][0] * inv0, oacc[nt][1] * inv0);
        *(float2*)&Aout[(size_t)(b * T + row0 + 8) * DM + d] =
            make_float2(oacc[nt][2] * inv1, oacc[nt][3] * inv1);
    }
}

// ---------------------------------------------------------------------------
extern "C" void kernel_launch(void* const* d_in, const int* in_sizes, int n_in,
                              void* d_out, int out_size)
{
    const float* q   = (const float*)d_in[0];
    const float* k   = (const float*)d_in[1];
    const float* v   = (const float*)d_in[2];
    const int*   msk = (const int*)  d_in[3];
    const float* Wq  = (const float*)d_in[4];
    const float* bq  = (const float*)d_in[5];
    const float* Wk  = (const float*)d_in[6];
    const float* bk  = (const float*)d_in[7];
    const float* Wv  = (const float*)d_in[8];
    const float* bv  = (const float*)d_in[9];
    const float* Wo  = (const float*)d_in[10];
    const float* bo  = (const float*)d_in[11];
    float* out = (float*)d_out;

    uint32_t *Qhi, *Qlo, *Khi, *Klo, *Vhi, *Vlo;
    float* Abuf;
    cudaGetSymbolAddress((void**)&Qhi, g_Qhi);
    cudaGetSymbolAddress((void**)&Qlo, g_Qlo);
    cudaGetSymbolAddress((void**)&Khi, g_Khi);
    cudaGetSymbolAddress((void**)&Klo, g_Klo);
    cudaGetSymbolAddress((void**)&Vhi, g_Vhi);
    cudaGetSymbolAddress((void**)&Vlo, g_Vlo);
    cudaGetSymbolAddress((void**)&Abuf, g_A);

    cudaFuncSetAttribute(gemm_mma,
                         cudaFuncAttributeMaxDynamicSharedMemorySize, GEMM_SMEM);
    cudaFuncSetAttribute(attn_mma,
                         cudaFuncAttributeMaxDynamicSharedMemorySize, ATTN_SMEM);

    dim3 gg(DM / 128, NT / 128);   // (8, 32)
    gemm_mma<<<gg, 256, GEMM_SMEM>>>(q, Wq, bq, nullptr, Qhi, Qlo, 1);
    gemm_mma<<<gg, 256, GEMM_SMEM>>>(k, Wk, bk, nullptr, Khi, Klo, 1);
    gemm_mma<<<gg, 256, GEMM_SMEM>>>(v, Wv, bv, nullptr, Vhi, Vlo, 2);

    dim3 ga(T / 128, NH, NB);      // (16, 16, 2)
    attn_mma<<<ga, 256, ATTN_SMEM>>>(Qhi, Qlo, Khi, Klo, Vhi, Vlo, msk, Abuf);

    gemm_mma<<<gg, 256, GEMM_SMEM>>>(Abuf, Wo, bo, out, nullptr, nullptr, 0);
}

// round 14
// speedup vs baseline: 1.9519x; 1.5986x over previous
#include <cuda_runtime.h>
#include <cuda_bf16.h>
#include <cstdint>
#include <math.h>

// Problem constants
#define NB 2
#define T 2048
#define DM 1024
#define NH 16
#define DK 64
#define NT (NB*T)           // 4096 rows

// ---- bf16 split helpers ----------------------------------------------------
__device__ __forceinline__ uint32_t packbf(float lo, float hi) {
    uint32_t r;
    asm("cvt.rn.bf16x2.f32 %0, %1, %2;" : "=r"(r) : "f"(hi), "f"(lo));
    return r;
}
// x -> element0 (low 16), y -> element1 (high 16); h + l reconstruct (x,y)
__device__ __forceinline__ void split2(float x, float y, uint32_t& h, uint32_t& l) {
    h = packbf(x, y);
    float hx = __uint_as_float(h << 16);
    float hy = __uint_as_float(h & 0xffff0000u);
    l = packbf(x - hx, y - hy);
}

// mma.sync m16n8k16 bf16 -> f32, D += A*B
#define MMA16816(d, a0, a1, a2, a3, b0, b1)                                    \
    asm volatile(                                                              \
        "mma.sync.aligned.m16n8k16.row.col.f32.bf16.bf16.f32 "                 \
        "{%0,%1,%2,%3}, {%4,%5,%6,%7}, {%8,%9}, {%0,%1,%2,%3};"                \
        : "+f"((d)[0]), "+f"((d)[1]), "+f"((d)[2]), "+f"((d)[3])               \
        : "r"(a0), "r"(a1), "r"(a2), "r"(a3), "r"(b0), "r"(b1))

// Scratch (device globals — no allocations allowed)
__device__ uint32_t g_Qhi[NB*NH*T*(DK/2)], g_Qlo[NB*NH*T*(DK/2)];
__device__ uint32_t g_Khi[NB*NH*T*(DK/2)], g_Klo[NB*NH*T*(DK/2)];
__device__ uint32_t g_Vhi[NB*NH*DK*(T/2)], g_Vlo[NB*NH*DK*(T/2)];
__device__ float    g_A  [NT*DM];
// pre-split staging (reused per GEMM)
__device__ uint32_t g_Ahi[NT*(DM/2)], g_Alo[NT*(DM/2)];      // A-side [m][kpair]
__device__ uint32_t g_Whi[DM*(DM/2)], g_Wlo[DM*(DM/2)];      // W^T    [n][kpair]

// ===========================================================================
// Pre-split kernels (run once per GEMM, memory-bound)
// ===========================================================================
__global__ __launch_bounds__(256) void split_a_kernel(
    const float* __restrict__ in, uint32_t* __restrict__ hi, uint32_t* __restrict__ lo)
{
    size_t i = (size_t)blockIdx.x * 256 + threadIdx.x;   // over NT*DM/2
    float2 v = *(const float2*)(in + i * 2);
    uint32_t h, l;
    split2(v.x, v.y, h, l);
    hi[i] = h;
    lo[i] = l;
}

// W [k][n] f32 -> hi/lo [n][kpair] u32, via smem transpose (64k x 32n tiles)
__global__ __launch_bounds__(256) void split_w_kernel(
    const float* __restrict__ W, uint32_t* __restrict__ hi, uint32_t* __restrict__ lo)
{
    __shared__ float s[64][33];
    int n0 = blockIdx.x * 32, k0 = blockIdx.y * 64;
    int tid = threadIdx.x;
    for (int i = tid; i < 64 * 32; i += 256) {
        int kk = i >> 5, nn = i & 31;
        s[kk][nn] = W[(size_t)(k0 + kk) * DM + n0 + nn];
    }
    __syncthreads();
    for (int i = tid; i < 32 * 32; i += 256) {
        int nn = i >> 5, kp = i & 31;
        uint32_t h, l;
        split2(s[kp * 2][nn], s[kp * 2 + 1][nn], h, l);
        size_t o = (size_t)(n0 + nn) * (DM / 2) + (k0 >> 1) + kp;
        hi[o] = h;
        lo[o] = l;
    }
}

// ===========================================================================
// GEMM via mma.sync bf16-split (pre-split operands): C = A @ B + bias
// Tile 128x128, 8 warps (4m x 2n), k-chunks of 32, double-buffered smem.
// mode 0: f32 row-major. mode 1: bf16 pairs head-split (Q,K).
// mode 2: bf16 pairs transposed [bh][d][t] (V).
// ===========================================================================
#define GSTR 20                        // b32 row stride (conflict-free frags)
#define GT_TILE_B (128 * GSTR * 4)     // 10240 bytes
#define GCHUNK_B  (4 * GT_TILE_B)      // Ah, Al, Bh, Bl
#define GEMM_SMEM (2 * GCHUNK_B)       // 81920 (covers 128x129 f32 Csm too)

__device__ __forceinline__ void g_load_regs(
    const uint32_t* __restrict__ Ahi, const uint32_t* __restrict__ Alo,
    const uint32_t* __restrict__ Bhi, const uint32_t* __restrict__ Blo,
    int bm, int bn, int c, uint2 ah[4], uint2 al[4], uint2 bh[4], uint2 bl[4])
{
    int tid = threadIdx.x;
#pragma unroll
    for (int j = 0; j < 4; j++) {
        int idx = tid + j * 256;            // 0..1023 = 128 rows x 8 uint2
        int row = idx >> 3, kf = idx & 7;
        size_t ao = (size_t)(bm + row) * (DM / 2) + c * 16 + kf * 2;
        ah[j] = *(const uint2*)(Ahi + ao);
        al[j] = *(const uint2*)(Alo + ao);
        size_t bo = (size_t)(bn + row) * (DM / 2) + c * 16 + kf * 2;
        bh[j] = *(const uint2*)(Bhi + bo);
        bl[j] = *(const uint2*)(Blo + bo);
    }
}

__device__ __forceinline__ void g_store_smem(
    char* buf, const uint2 ah[4], const uint2 al[4], const uint2 bh[4], const uint2 bl[4])
{
    uint32_t* Ah = (uint32_t*)buf;
    uint32_t* Al = (uint32_t*)(buf + GT_TILE_B);
    uint32_t* Bh = (uint32_t*)(buf + 2 * GT_TILE_B);
    uint32_t* Bl = (uint32_t*)(buf + 3 * GT_TILE_B);
    int tid = threadIdx.x;
#pragma unroll
    for (int j = 0; j < 4; j++) {
        int idx = tid + j * 256;
        int row = idx >> 3, kf = idx & 7;
        Ah[row * GSTR + kf * 2]     = ah[j].x;
        Ah[row * GSTR + kf * 2 + 1] = ah[j].y;
        Al[row * GSTR + kf * 2]     = al[j].x;
        Al[row * GSTR + kf * 2 + 1] = al[j].y;
        Bh[row * GSTR + kf * 2]     = bh[j].x;
        Bh[row * GSTR + kf * 2 + 1] = bh[j].y;
        Bl[row * GSTR + kf * 2]     = bl[j].x;
        Bl[row * GSTR + kf * 2 + 1] = bl[j].y;
    }
}

__global__ __launch_bounds__(256) void gemm_mma(
    const uint32_t* __restrict__ Ahi, const uint32_t* __restrict__ Alo,
    const uint32_t* __restrict__ Bhi, const uint32_t* __restrict__ Blo,
    const float* __restrict__ bias, float* __restrict__ C,
    uint32_t* __restrict__ Chi, uint32_t* __restrict__ Clo, int mode)
{
    extern __shared__ char sb[];
    int tid = threadIdx.x;
    int wid = tid >> 5, lane = tid & 31;
    int lq = lane >> 2, lr = lane & 3;
    int wm = wid & 3, wn = wid >> 2;
    int bn = blockIdx.x * 128;
    int bm = blockIdx.y * 128;

    float acc[2][8][4];
#pragma unroll
    for (int mt = 0; mt < 2; mt++)
#pragma unroll
        for (int nt = 0; nt < 8; nt++)
#pragma unroll
            for (int i = 0; i < 4; i++) acc[mt][nt][i] = 0.f;

    {
        uint2 ah[4], al[4], bh[4], bl[4];
        g_load_regs(Ahi, Alo, Bhi, Blo, bm, bn, 0, ah, al, bh, bl);
        g_store_smem(sb, ah, al, bh, bl);
    }
    __syncthreads();

    for (int c = 0; c < 32; c++) {
        int p = c & 1;
        uint2 ah[4], al[4], bh[4], bl[4];
        bool more = (c + 1 < 32);
        if (more) g_load_regs(Ahi, Alo, Bhi, Blo, bm, bn, c + 1, ah, al, bh, bl);

        char* buf = sb + p * GCHUNK_B;
        const uint32_t* Ah32 = (const uint32_t*)buf;
        const uint32_t* Al32 = (const uint32_t*)(buf + GT_TILE_B);
        const uint32_t* Bh32 = (const uint32_t*)(buf + 2 * GT_TILE_B);
        const uint32_t* Bl32 = (const uint32_t*)(buf + 3 * GT_TILE_B);

#pragma unroll
        for (int s = 0; s < 2; s++) {
            int ka = s * 8 + lr;
            uint32_t fah[2][4], fal[2][4];
#pragma unroll
            for (int mt = 0; mt < 2; mt++) {
                int r = wm * 32 + mt * 16 + lq;
                fah[mt][0] = Ah32[r * GSTR + ka];
                fah[mt][1] = Ah32[(r + 8) * GSTR + ka];
                fah[mt][2] = Ah32[r * GSTR + ka + 4];
                fah[mt][3] = Ah32[(r + 8) * GSTR + ka + 4];
                fal[mt][0] = Al32[r * GSTR + ka];
                fal[mt][1] = Al32[(r + 8) * GSTR + ka];
                fal[mt][2] = Al32[r * GSTR + ka + 4];
                fal[mt][3] = Al32[(r + 8) * GSTR + ka + 4];
            }
#pragma unroll
            for (int nt = 0; nt < 8; nt++) {
                int rn = wn * 64 + nt * 8 + lq;
                uint32_t fbh0 = Bh32[rn * GSTR + ka];
                uint32_t fbh1 = Bh32[rn * GSTR + ka + 4];
                uint32_t fbl0 = Bl32[rn * GSTR + ka];
                uint32_t fbl1 = Bl32[rn * GSTR + ka + 4];
#pragma unroll
                for (int mt = 0; mt < 2; mt++) {
                    MMA16816(acc[mt][nt], fah[mt][0], fah[mt][1], fah[mt][2], fah[mt][3], fbh0, fbh1);
                    MMA16816(acc[mt][nt], fah[mt][0], fah[mt][1], fah[mt][2], fah[mt][3], fbl0, fbl1);
                    MMA16816(acc[mt][nt], fal[mt][0], fal[mt][1], fal[mt][2], fal[mt][3], fbh0, fbh1);
                }
            }
        }
        if (more) g_store_smem(sb + (p ^ 1) * GCHUNK_B, ah, al, bh, bl);
        __syncthreads();
    }

    // ---- epilogue ----
    if (mode == 0) {
#pragma unroll
        for (int mt = 0; mt < 2; mt++)
#pragma unroll
            for (int nt = 0; nt < 8; nt++) {
                int m = bm + wm * 32 + mt * 16 + lq;
                int n = bn + wn * 64 + nt * 8 + lr * 2;
                float b0 = bias[n], b1 = bias[n + 1];
                *(float2*)&C[(size_t)m * DM + n] =
                    make_float2(acc[mt][nt][0] + b0, acc[mt][nt][1] + b1);
                *(float2*)&C[(size_t)(m + 8) * DM + n] =
                    make_float2(acc[mt][nt][2] + b0, acc[mt][nt][3] + b1);
            }
    } else if (mode == 1) {
#pragma unroll
        for (int mt = 0; mt < 2; mt++)
#pragma unroll
            for (int nt = 0; nt < 8; nt++) {
                int m = bm + wm * 32 + mt * 16 + lq;
                int n = bn + wn * 64 + nt * 8 + lr * 2;
                float b0 = bias[n], b1 = bias[n + 1];
                int hh = n >> 6, d = n & (DK - 1);
#pragma unroll
                for (int rr = 0; rr < 2; rr++) {
                    int mm = m + rr * 8;
                    int bb = mm >> 11, t = mm & (T - 1);
                    float v0 = acc[mt][nt][rr * 2 + 0] + b0;
                    float v1 = acc[mt][nt][rr * 2 + 1] + b1;
                    uint32_t h, l;
                    split2(v0, v1, h, l);
                    size_t o = ((size_t)(bb * NH + hh) * T + t) * (DK / 2) + (d >> 1);
                    Chi[o] = h;
                    Clo[o] = l;
                }
            }
    } else {
        // mode 2: stage via smem, write transposed bf16 pairs [bh][d][t]
        float* Csm = (float*)sb;   // [128][129]
#pragma unroll
        for (int mt = 0; mt < 2; mt++)
#pragma unroll
            for (int nt = 0; nt < 8; nt++) {
                int ml = wm * 32 + mt * 16 + lq;
                int nl = wn * 64 + nt * 8 + lr * 2;
                float b0 = bias[bn + nl], b1 = bias[bn + nl + 1];
                Csm[ml * 129 + nl]           = acc[mt][nt][0] + b0;
                Csm[ml * 129 + nl + 1]       = acc[mt][nt][1] + b1;
                Csm[(ml + 8) * 129 + nl]     = acc[mt][nt][2] + b0;
                Csm[(ml + 8) * 129 + nl + 1] = acc[mt][nt][3] + b1;
            }
        __syncthreads();
        int bb = bm >> 11;
        int tbase = (bm & (T - 1)) >> 1;
        for (int idx = tid; idx < 128 * 64; idx += 256) {
            int nl = idx >> 6;
            int tp = idx & 63;
            uint32_t h, l;
            split2(Csm[(tp * 2) * 129 + nl], Csm[(tp * 2 + 1) * 129 + nl], h, l);
            int n = bn + nl;
            int hh = n >> 6, d = n & (DK - 1);
            size_t o = ((size_t)(bb * NH + hh) * DK + d) * (T / 2) + tbase + tp;
            Chi[o] = h;
            Clo[o] = l;
        }
    }
}

// ===========================================================================
// Flash attention via mma.sync bf16-split, 64-key half-tiles for occupancy.
// 256 threads, 8 warps; warp w owns q-rows w*16..+15.
// ===========================================================================
#define QSTR 36
#define VSTR 68
#define SM_QH 0
#define SM_QL (SM_QH + 128*QSTR*4)
#define SM_KH (SM_QL + 128*QSTR*4)
#define SM_KL (SM_KH + 128*QSTR*4)
#define SM_VH (SM_KL + 128*QSTR*4)
#define SM_VL (SM_VH + 64*VSTR*4)
#define SM_MK (SM_VL + 64*VSTR*4)
#define ATTN_SMEM (SM_MK + 128*4)

__global__ __launch_bounds__(256, 2) void attn_mma(
    const uint32_t* __restrict__ Qhi, const uint32_t* __restrict__ Qlo,
    const uint32_t* __restrict__ Khi, const uint32_t* __restrict__ Klo,
    const uint32_t* __restrict__ Vhi, const uint32_t* __restrict__ Vlo,
    const int* __restrict__ mask, float* __restrict__ Aout)
{
    extern __shared__ char sb[];
    uint32_t* Qh32 = (uint32_t*)(sb + SM_QH);
    uint32_t* Ql32 = (uint32_t*)(sb + SM_QL);
    uint32_t* Kh32 = (uint32_t*)(sb + SM_KH);
    uint32_t* Kl32 = (uint32_t*)(sb + SM_KL);
    uint32_t* Vh32 = (uint32_t*)(sb + SM_VH);
    uint32_t* Vl32 = (uint32_t*)(sb + SM_VL);
    float*    Mk   = (float*)   (sb + SM_MK);

    int tid = threadIdx.x;
    int wid = tid >> 5, lane = tid & 31;
    int lq = lane >> 2, lr = lane & 3;
    int m0 = wid * 16;
    int q0 = blockIdx.x * 128;
    int h  = blockIdx.y;
    int b  = blockIdx.z;
    int bh = b * NH + h;

    {
        const uint32_t* qh = Qhi + ((size_t)bh * T + q0) * (DK / 2);
        const uint32_t* ql = Qlo + ((size_t)bh * T + q0) * (DK / 2);
        for (int idx = tid; idx < 128 * 32; idx += 256) {
            int r = idx >> 5, cc = idx & 31;
            Qh32[r * QSTR + cc] = qh[r * 32 + cc];
            Ql32[r * QSTR + cc] = ql[r * 32 + cc];
        }
    }

    float m_r0 = -1e30f, m_r1 = -1e30f, l_0 = 0.f, l_1 = 0.f;
    float oacc[8][4];
#pragma unroll
    for (int nt = 0; nt < 8; nt++)
#pragma unroll
        for (int i = 0; i < 4; i++) oacc[nt][i] = 0.f;

    const float scale = 0.125f;

    for (int k0 = 0; k0 < T; k0 += 128) {
        __syncthreads();
        {
            const uint32_t* kh = Khi + ((size_t)bh * T + k0) * (DK / 2);
            const uint32_t* kl = Klo + ((size_t)bh * T + k0) * (DK / 2);
            for (int idx = tid; idx < 128 * 32; idx += 256) {
                int r = idx >> 5, cc = idx & 31;
                Kh32[r * QSTR + cc] = kh[r * 32 + cc];
                Kl32[r * QSTR + cc] = kl[r * 32 + cc];
            }
            const uint32_t* vh = Vhi + (size_t)bh * DK * (T / 2) + (k0 >> 1);
            const uint32_t* vl = Vlo + (size_t)bh * DK * (T / 2) + (k0 >> 1);
            for (int idx = tid; idx < 64 * 64; idx += 256) {
                int d = idx >> 6, j = idx & 63;
                Vh32[d * VSTR + j] = vh[(size_t)d * (T / 2) + j];
                Vl32[d * VSTR + j] = vl[(size_t)d * (T / 2) + j];
            }
            if (tid < 128)
                Mk[tid] = mask[b * T + k0 + tid] ? 0.f : -1e30f;
        }
        __syncthreads();

#pragma unroll
        for (int half = 0; half < 2; half++) {
            // ---- score: S = Q K^T (64 keys) ----
            float sacc[8][4];
#pragma unroll
            for (int nt = 0; nt < 8; nt++)
#pragma unroll
                for (int i = 0; i < 4; i++) sacc[nt][i] = 0.f;

#pragma unroll
            for (int s = 0; s < 4; s++) {
                int ka = s * 8 + lr;
                int r = m0 + lq;
                uint32_t ah0 = Qh32[r * QSTR + ka],     ah1 = Qh32[(r + 8) * QSTR + ka];
                uint32_t ah2 = Qh32[r * QSTR + ka + 4], ah3 = Qh32[(r + 8) * QSTR + ka + 4];
                uint32_t al0 = Ql32[r * QSTR + ka],     al1 = Ql32[(r + 8) * QSTR + ka];
                uint32_t al2 = Ql32[r * QSTR + ka + 4], al3 = Ql32[(r + 8) * QSTR + ka + 4];
#pragma unroll
                for (int nt = 0; nt < 8; nt++) {
                    int rn = half * 64 + nt * 8 + lq;
                    uint32_t bh0 = Kh32[rn * QSTR + ka];
                    uint32_t bh1 = Kh32[rn * QSTR + ka + 4];
                    uint32_t bl0 = Kl32[rn * QSTR + ka];
                    uint32_t bl1 = Kl32[rn * QSTR + ka + 4];
                    MMA16816(sacc[nt], ah0, ah1, ah2, ah3, bh0, bh1);
                    MMA16816(sacc[nt], ah0, ah1, ah2, ah3, bl0, bl1);
                    MMA16816(sacc[nt], al0, al1, al2, al3, bh0, bh1);
                }
            }

            // ---- online softmax over these 64 cols ----
            float mx0 = -1e30f, mx1 = -1e30f;
#pragma unroll
            for (int nt = 0; nt < 8; nt++) {
                int cc = half * 64 + nt * 8 + lr * 2;
                float k0m = Mk[cc], k1m = Mk[cc + 1];
                float s0 = sacc[nt][0] * scale + k0m;
                float s1 = sacc[nt][1] * scale + k1m;
                float s2 = sacc[nt][2] * scale + k0m;
                float s3 = sacc[nt][3] * scale + k1m;
                sacc[nt][0] = s0; sacc[nt][1] = s1; sacc[nt][2] = s2; sacc[nt][3] = s3;
                mx0 = fmaxf(mx0, fmaxf(s0, s1));
                mx1 = fmaxf(mx1, fmaxf(s2, s3));
            }
            mx0 = fmaxf(mx0, __shfl_xor_sync(0xffffffffu, mx0, 1));
            mx0 = fmaxf(mx0, __shfl_xor_sync(0xffffffffu, mx0, 2));
            mx1 = fmaxf(mx1, __shfl_xor_sync(0xffffffffu, mx1, 1));
            mx1 = fmaxf(mx1, __shfl_xor_sync(0xffffffffu, mx1, 2));
            float m_new0 = fmaxf(m_r0, mx0);
            float m_new1 = fmaxf(m_r1, mx1);

            float sum0 = 0.f, sum1 = 0.f;
#pragma unroll
            for (int nt = 0; nt < 8; nt++) {
                float p0 = __expf(sacc[nt][0] - m_new0);
                float p1 = __expf(sacc[nt][1] - m_new0);
                float p2 = __expf(sacc[nt][2] - m_new1);
                float p3 = __expf(sacc[nt][3] - m_new1);
                sacc[nt][0] = p0; sacc[nt][1] = p1; sacc[nt][2] = p2; sacc[nt][3] = p3;
                sum0 += p0 + p1;
                sum1 += p2 + p3;
            }
            sum0 += __shfl_xor_sync(0xffffffffu, sum0, 1);
            sum0 += __shfl_xor_sync(0xffffffffu, sum0, 2);
            sum1 += __shfl_xor_sync(0xffffffffu, sum1, 1);
            sum1 += __shfl_xor_sync(0xffffffffu, sum1, 2);

            float alpha0 = __expf(m_r0 - m_new0);
            float alpha1 = __expf(m_r1 - m_new1);
            l_0 = l_0 * alpha0 + sum0;
            l_1 = l_1 * alpha1 + sum1;
            m_r0 = m_new0;
            m_r1 = m_new1;
#pragma unroll
            for (int nt = 0; nt < 8; nt++) {
                oacc[nt][0] *= alpha0; oacc[nt][1] *= alpha0;
                oacc[nt][2] *= alpha1; oacc[nt][3] *= alpha1;
            }

            // ---- PV: O += P V (P from registers, 64-key k-dim) ----
#pragma unroll
            for (int kt = 0; kt < 4; kt++) {
                uint32_t pah[4], pal[4];
                split2(sacc[2 * kt][0],     sacc[2 * kt][1],     pah[0], pal[0]);
                split2(sacc[2 * kt][2],     sacc[2 * kt][3],     pah[1], pal[1]);
                split2(sacc[2 * kt + 1][0], sacc[2 * kt + 1][1], pah[2], pal[2]);
                split2(sacc[2 * kt + 1][2], sacc[2 * kt + 1][3], pah[3], pal[3]);
                int koff = half * 32 + kt * 8 + lr;
#pragma unroll
                for (int nt = 0; nt < 8; nt++) {
                    int rn = nt * 8 + lq;
                    uint32_t vh0 = Vh32[rn * VSTR + koff];
                    uint32_t vh1 = Vh32[rn * VSTR + koff + 4];
                    uint32_t vl0 = Vl32[rn * VSTR + koff];
                    uint32_t vl1 = Vl32[rn * VSTR + koff + 4];
                    MMA16816(oacc[nt], pah[0], pah[1], pah[2], pah[3], vh0, vh1);
                    MMA16816(oacc[nt], pah[0], pah[1], pah[2], pah[3], vl0, vl1);
                    MMA16816(oacc[nt], pal[0], pal[1], pal[2], pal[3], vh0, vh1);
                }
            }
        }
    }

    // ---- write A [N*T][DM] ----
    float inv0 = 1.f / l_0, inv1 = 1.f / l_1;
    int row0 = q0 + m0 + lq;
#pragma unroll
    for (int nt = 0; nt < 8; nt++) {
        int d = h * DK + nt * 8 + lr * 2;
        *(float2*)&Aout[(size_t)(b * T + row0) * DM + d] =
            make_float2(oacc[nt][0] * inv0, oacc[nt][1] * inv0);
        *(float2*)&Aout[(size_t)(b * T + row0 + 8) * DM + d] =
            make_float2(oacc[nt][2] * inv1, oacc[nt][3] * inv1);
    }
}

// ---------------------------------------------------------------------------
extern "C" void kernel_launch(void* const* d_in, const int* in_sizes, int n_in,
                              void* d_out, int out_size)
{
    const float* q   = (const float*)d_in[0];
    const float* k   = (const float*)d_in[1];
    const float* v   = (const float*)d_in[2];
    const int*   msk = (const int*)  d_in[3];
    const float* Wq  = (const float*)d_in[4];
    const float* bq  = (const float*)d_in[5];
    const float* Wk  = (const float*)d_in[6];
    const float* bk  = (const float*)d_in[7];
    const float* Wv  = (const float*)d_in[8];
    const float* bv  = (const float*)d_in[9];
    const float* Wo  = (const float*)d_in[10];
    const float* bo  = (const float*)d_in[11];
    float* out = (float*)d_out;

    uint32_t *Qhi, *Qlo, *Khi, *Klo, *Vhi, *Vlo, *Ahi, *Alo, *Whi, *Wlo;
    float* Abuf;
    cudaGetSymbolAddress((void**)&Qhi, g_Qhi);
    cudaGetSymbolAddress((void**)&Qlo, g_Qlo);
    cudaGetSymbolAddress((void**)&Khi, g_Khi);
    cudaGetSymbolAddress((void**)&Klo, g_Klo);
    cudaGetSymbolAddress((void**)&Vhi, g_Vhi);
    cudaGetSymbolAddress((void**)&Vlo, g_Vlo);
    cudaGetSymbolAddress((void**)&Ahi, g_Ahi);
    cudaGetSymbolAddress((void**)&Alo, g_Alo);
    cudaGetSymbolAddress((void**)&Whi, g_Whi);
    cudaGetSymbolAddress((void**)&Wlo, g_Wlo);
    cudaGetSymbolAddress((void**)&Abuf, g_A);

    cudaFuncSetAttribute(gemm_mma,
                         cudaFuncAttributeMaxDynamicSharedMemorySize, GEMM_SMEM);
    cudaFuncSetAttribute(attn_mma,
                         cudaFuncAttributeMaxDynamicSharedMemorySize, ATTN_SMEM);

    dim3 gg(DM / 128, NT / 128);   // (8, 32)
    dim3 gw(DM / 32, DM / 64);     // (32, 16)
    int ga_blocks = NT * (DM / 2) / 256;   // 8192

    split_w_kernel<<<gw, 256>>>(Wq, Whi, Wlo);
    split_a_kernel<<<ga_blocks, 256>>>(q, Ahi, Alo);
    gemm_mma<<<gg, 256, GEMM_SMEM>>>(Ahi, Alo, Whi, Wlo, bq, nullptr, Qhi, Qlo, 1);

    split_w_kernel<<<gw, 256>>>(Wk, Whi, Wlo);
    split_a_kernel<<<ga_blocks, 256>>>(k, Ahi, Alo);
    gemm_mma<<<gg, 256, GEMM_SMEM>>>(Ahi, Alo, Whi, Wlo, bk, nullptr, Khi, Klo, 1);

    split_w_kernel<<<gw, 256>>>(Wv, Whi, Wlo);
    split_a_kernel<<<ga_blocks, 256>>>(v, Ahi, Alo);
    gemm_mma<<<gg, 256, GEMM_SMEM>>>(Ahi, Alo, Whi, Wlo, bv, nullptr, Vhi, Vlo, 2);

    dim3 gat(T / 128, NH, NB);     // (16, 16, 2)
    attn_mma<<<gat, 256, ATTN_SMEM>>>(Qhi, Qlo, Khi, Klo, Vhi, Vlo, msk, Abuf);

    split_w_kernel<<<gw, 256>>>(Wo, Whi, Wlo);
    split_a_kernel<<<ga_blocks, 256>>>(Abuf, Ahi, Alo);
    gemm_mma<<<gg, 256, GEMM_SMEM>>>(Ahi, Alo, Whi, Wlo, bo, out, nullptr, nullptr, 0);
}

// round 15
// speedup vs baseline: 2.2076x; 1.1310x over previous
#include <cuda_runtime.h>
#include <cuda_bf16.h>
#include <cstdint>
#include <math.h>

// Problem constants
#define NB 2
#define T 2048
#define DM 1024
#define NH 16
#define DK 64
#define NT (NB*T)           // 4096 rows

// ---- bf16 split helpers ----------------------------------------------------
__device__ __forceinline__ uint32_t packbf(float lo, float hi) {
    uint32_t r;
    asm("cvt.rn.bf16x2.f32 %0, %1, %2;" : "=r"(r) : "f"(hi), "f"(lo));
    return r;
}
__device__ __forceinline__ void split2(float x, float y, uint32_t& h, uint32_t& l) {
    h = packbf(x, y);
    float hx = __uint_as_float(h << 16);
    float hy = __uint_as_float(h & 0xffff0000u);
    l = packbf(x - hx, y - hy);
}

// mma.sync m16n8k16 bf16 -> f32, D += A*B
#define MMA16816(d, a0, a1, a2, a3, b0, b1)                                    \
    asm volatile(                                                              \
        "mma.sync.aligned.m16n8k16.row.col.f32.bf16.bf16.f32 "                 \
        "{%0,%1,%2,%3}, {%4,%5,%6,%7}, {%8,%9}, {%0,%1,%2,%3};"                \
        : "+f"((d)[0]), "+f"((d)[1]), "+f"((d)[2]), "+f"((d)[3])               \
        : "r"(a0), "r"(a1), "r"(a2), "r"(a3), "r"(b0), "r"(b1))

// ---- cp.async helpers ------------------------------------------------------
__device__ __forceinline__ void cp_async8(uint32_t saddr, const void* g) {
    asm volatile("cp.async.ca.shared.global [%0], [%1], 8;" :: "r"(saddr), "l"(g));
}
#define CP_COMMIT() asm volatile("cp.async.commit_group;" ::: "memory")
#define CP_WAIT0()  asm volatile("cp.async.wait_group 0;" ::: "memory")
#define CP_WAIT1()  asm volatile("cp.async.wait_group 1;" ::: "memory")

__device__ __forceinline__ uint32_t smem_u32p(const void* p) {
    uint32_t a;
    asm("{ .reg .u64 t; cvta.to.shared.u64 t, %1; cvt.u32.u64 %0, t; }"
        : "=r"(a) : "l"(p));
    return a;
}

// Scratch (device globals — no allocations allowed)
__device__ uint32_t g_Qhi[NB*NH*T*(DK/2)], g_Qlo[NB*NH*T*(DK/2)];
__device__ uint32_t g_Khi[NB*NH*T*(DK/2)], g_Klo[NB*NH*T*(DK/2)];
__device__ uint32_t g_Vhi[NB*NH*DK*(T/2)], g_Vlo[NB*NH*DK*(T/2)];
__device__ uint32_t g_Ahi[NT*(DM/2)], g_Alo[NT*(DM/2)];      // A-side [m][kpair]
__device__ uint32_t g_Whi[DM*(DM/2)], g_Wlo[DM*(DM/2)];      // W^T    [n][kpair]

// ===========================================================================
// Pre-split kernels
// ===========================================================================
__global__ __launch_bounds__(256) void split_a_kernel(
    const float* __restrict__ in, uint32_t* __restrict__ hi, uint32_t* __restrict__ lo)
{
    size_t i = (size_t)blockIdx.x * 256 + threadIdx.x;
    float2 v = *(const float2*)(in + i * 2);
    uint32_t h, l;
    split2(v.x, v.y, h, l);
    hi[i] = h;
    lo[i] = l;
}

__global__ __launch_bounds__(256) void split_w_kernel(
    const float* __restrict__ W, uint32_t* __restrict__ hi, uint32_t* __restrict__ lo)
{
    __shared__ float s[64][33];
    int n0 = blockIdx.x * 32, k0 = blockIdx.y * 64;
    int tid = threadIdx.x;
    for (int i = tid; i < 64 * 32; i += 256) {
        int kk = i >> 5, nn = i & 31;
        s[kk][nn] = W[(size_t)(k0 + kk) * DM + n0 + nn];
    }
    __syncthreads();
    for (int i = tid; i < 32 * 32; i += 256) {
        int nn = i >> 5, kp = i & 31;
        uint32_t h, l;
        split2(s[kp * 2][nn], s[kp * 2 + 1][nn], h, l);
        size_t o = (size_t)(n0 + nn) * (DM / 2) + (k0 >> 1) + kp;
        hi[o] = h;
        lo[o] = l;
    }
}

// ===========================================================================
// GEMM via mma.sync bf16-split, cp.async double-buffered, occ 2.
// Tile 128x128, 8 warps (4m x 2n), k-chunks of 32.
// mode 0: f32 row-major. mode 1: bf16 pairs head-split (Q,K).
// mode 2: bf16 pairs transposed [bh][d][t] (V).
// ===========================================================================
#define GSTR 20                        // b32 row stride (conflict-free frags)
#define GT_TILE_B (128 * GSTR * 4)     // 10240 bytes
#define GCHUNK_B  (4 * GT_TILE_B)      // Ah, Al, Bh, Bl
#define GEMM_SMEM (2 * GCHUNK_B)       // 81920 (covers 128x129 f32 Csm)

__device__ __forceinline__ void g_issue_chunk(
    const uint32_t* __restrict__ Ahi, const uint32_t* __restrict__ Alo,
    const uint32_t* __restrict__ Bhi, const uint32_t* __restrict__ Blo,
    int bm, int bn, int c, uint32_t sbuf)
{
    int tid = threadIdx.x;
#pragma unroll
    for (int j = 0; j < 4; j++) {
        int idx = tid + j * 256;            // 0..1023 = 128 rows x 8 u32-pairs
        int row = idx >> 3, kf = idx & 7;
        uint32_t so = (uint32_t)(row * GSTR + kf * 2) * 4;
        size_t ao = (size_t)(bm + row) * (DM / 2) + c * 16 + kf * 2;
        size_t bo = (size_t)(bn + row) * (DM / 2) + c * 16 + kf * 2;
        cp_async8(sbuf + so,                 Ahi + ao);
        cp_async8(sbuf + GT_TILE_B + so,     Alo + ao);
        cp_async8(sbuf + 2 * GT_TILE_B + so, Bhi + bo);
        cp_async8(sbuf + 3 * GT_TILE_B + so, Blo + bo);
    }
}

__global__ __launch_bounds__(256, 2) void gemm_mma(
    const uint32_t* __restrict__ Ahi, const uint32_t* __restrict__ Alo,
    const uint32_t* __restrict__ Bhi, const uint32_t* __restrict__ Blo,
    const float* __restrict__ bias, float* __restrict__ C,
    uint32_t* __restrict__ Chi, uint32_t* __restrict__ Clo, int mode)
{
    extern __shared__ char sb[];
    int tid = threadIdx.x;
    int wid = tid >> 5, lane = tid & 31;
    int lq = lane >> 2, lr = lane & 3;
    int wm = wid & 3, wn = wid >> 2;
    int bn = blockIdx.x * 128;
    int bm = blockIdx.y * 128;
    uint32_t sbu = smem_u32p(sb);

    float acc[2][8][4];
#pragma unroll
    for (int mt = 0; mt < 2; mt++)
#pragma unroll
        for (int nt = 0; nt < 8; nt++)
#pragma unroll
            for (int i = 0; i < 4; i++) acc[mt][nt][i] = 0.f;

    g_issue_chunk(Ahi, Alo, Bhi, Blo, bm, bn, 0, sbu);
    CP_COMMIT();

    for (int c = 0; c < 32; c++) {
        int p = c & 1;
        bool more = (c + 1 < 32);
        if (more) {
            g_issue_chunk(Ahi, Alo, Bhi, Blo, bm, bn, c + 1, sbu + (p ^ 1) * GCHUNK_B);
            CP_COMMIT();
            CP_WAIT1();
        } else {
            CP_WAIT0();
        }
        __syncthreads();

        char* buf = sb + p * GCHUNK_B;
        const uint32_t* Ah32 = (const uint32_t*)buf;
        const uint32_t* Al32 = (const uint32_t*)(buf + GT_TILE_B);
        const uint32_t* Bh32 = (const uint32_t*)(buf + 2 * GT_TILE_B);
        const uint32_t* Bl32 = (const uint32_t*)(buf + 3 * GT_TILE_B);

#pragma unroll
        for (int s = 0; s < 2; s++) {
            int ka = s * 8 + lr;
            uint32_t fah[2][4], fal[2][4];
#pragma unroll
            for (int mt = 0; mt < 2; mt++) {
                int r = wm * 32 + mt * 16 + lq;
                fah[mt][0] = Ah32[r * GSTR + ka];
                fah[mt][1] = Ah32[(r + 8) * GSTR + ka];
                fah[mt][2] = Ah32[r * GSTR + ka + 4];
                fah[mt][3] = Ah32[(r + 8) * GSTR + ka + 4];
                fal[mt][0] = Al32[r * GSTR + ka];
                fal[mt][1] = Al32[(r + 8) * GSTR + ka];
                fal[mt][2] = Al32[r * GSTR + ka + 4];
                fal[mt][3] = Al32[(r + 8) * GSTR + ka + 4];
            }
#pragma unroll
            for (int nt = 0; nt < 8; nt++) {
                int rn = wn * 64 + nt * 8 + lq;
                uint32_t fbh0 = Bh32[rn * GSTR + ka];
                uint32_t fbh1 = Bh32[rn * GSTR + ka + 4];
                uint32_t fbl0 = Bl32[rn * GSTR + ka];
                uint32_t fbl1 = Bl32[rn * GSTR + ka + 4];
#pragma unroll
                for (int mt = 0; mt < 2; mt++) {
                    MMA16816(acc[mt][nt], fah[mt][0], fah[mt][1], fah[mt][2], fah[mt][3], fbh0, fbh1);
                    MMA16816(acc[mt][nt], fah[mt][0], fah[mt][1], fah[mt][2], fah[mt][3], fbl0, fbl1);
                    MMA16816(acc[mt][nt], fal[mt][0], fal[mt][1], fal[mt][2], fal[mt][3], fbh0, fbh1);
                }
            }
        }
        __syncthreads();
    }

    // ---- epilogue ----
    if (mode == 0) {
#pragma unroll
        for (int mt = 0; mt < 2; mt++)
#pragma unroll
            for (int nt = 0; nt < 8; nt++) {
                int m = bm + wm * 32 + mt * 16 + lq;
                int n = bn + wn * 64 + nt * 8 + lr * 2;
                float b0 = bias[n], b1 = bias[n + 1];
                *(float2*)&C[(size_t)m * DM + n] =
                    make_float2(acc[mt][nt][0] + b0, acc[mt][nt][1] + b1);
                *(float2*)&C[(size_t)(m + 8) * DM + n] =
                    make_float2(acc[mt][nt][2] + b0, acc[mt][nt][3] + b1);
            }
    } else if (mode == 1) {
#pragma unroll
        for (int mt = 0; mt < 2; mt++)
#pragma unroll
            for (int nt = 0; nt < 8; nt++) {
                int m = bm + wm * 32 + mt * 16 + lq;
                int n = bn + wn * 64 + nt * 8 + lr * 2;
                float b0 = bias[n], b1 = bias[n + 1];
                int hh = n >> 6, d = n & (DK - 1);
#pragma unroll
                for (int rr = 0; rr < 2; rr++) {
                    int mm = m + rr * 8;
                    int bb = mm >> 11, t = mm & (T - 1);
                    float v0 = acc[mt][nt][rr * 2 + 0] + b0;
                    float v1 = acc[mt][nt][rr * 2 + 1] + b1;
                    uint32_t h, l;
                    split2(v0, v1, h, l);
                    size_t o = ((size_t)(bb * NH + hh) * T + t) * (DK / 2) + (d >> 1);
                    Chi[o] = h;
                    Clo[o] = l;
                }
            }
    } else {
        float* Csm = (float*)sb;   // [128][129]
#pragma unroll
        for (int mt = 0; mt < 2; mt++)
#pragma unroll
            for (int nt = 0; nt < 8; nt++) {
                int ml = wm * 32 + mt * 16 + lq;
                int nl = wn * 64 + nt * 8 + lr * 2;
                float b0 = bias[bn + nl], b1 = bias[bn + nl + 1];
                Csm[ml * 129 + nl]           = acc[mt][nt][0] + b0;
                Csm[ml * 129 + nl + 1]       = acc[mt][nt][1] + b1;
                Csm[(ml + 8) * 129 + nl]     = acc[mt][nt][2] + b0;
                Csm[(ml + 8) * 129 + nl + 1] = acc[mt][nt][3] + b1;
            }
        __syncthreads();
        int bb = bm >> 11;
        int tbase = (bm & (T - 1)) >> 1;
        for (int idx = tid; idx < 128 * 64; idx += 256) {
            int nl = idx >> 6;
            int tp = idx & 63;
            uint32_t h, l;
            split2(Csm[(tp * 2) * 129 + nl], Csm[(tp * 2 + 1) * 129 + nl], h, l);
            int n = bn + nl;
            int hh = n >> 6, d = n & (DK - 1);
            size_t o = ((size_t)(bb * NH + hh) * DK + d) * (T / 2) + tbase + tp;
            Chi[o] = h;
            Clo[o] = l;
        }
    }
}

// ===========================================================================
// Flash attention via mma.sync bf16-split, 64-key half-tiles, occ 2,
// cp.async tile loads, split-pair output (feeds final GEMM directly).
// ===========================================================================
#define QSTR 36
#define VSTR 68
#define SM_QH 0
#define SM_QL (SM_QH + 128*QSTR*4)
#define SM_KH (SM_QL + 128*QSTR*4)
#define SM_KL (SM_KH + 128*QSTR*4)
#define SM_VH (SM_KL + 128*QSTR*4)
#define SM_VL (SM_VH + 64*VSTR*4)
#define SM_MK (SM_VL + 64*VSTR*4)
#define ATTN_SMEM (SM_MK + 128*4)

__global__ __launch_bounds__(256, 2) void attn_mma(
    const uint32_t* __restrict__ Qhi, const uint32_t* __restrict__ Qlo,
    const uint32_t* __restrict__ Khi, const uint32_t* __restrict__ Klo,
    const uint32_t* __restrict__ Vhi, const uint32_t* __restrict__ Vlo,
    const int* __restrict__ mask,
    uint32_t* __restrict__ Ohi, uint32_t* __restrict__ Olo)
{
    extern __shared__ char sb[];
    uint32_t* Qh32 = (uint32_t*)(sb + SM_QH);
    uint32_t* Ql32 = (uint32_t*)(sb + SM_QL);
    uint32_t* Kh32 = (uint32_t*)(sb + SM_KH);
    uint32_t* Kl32 = (uint32_t*)(sb + SM_KL);
    uint32_t* Vh32 = (uint32_t*)(sb + SM_VH);
    uint32_t* Vl32 = (uint32_t*)(sb + SM_VL);
    float*    Mk   = (float*)   (sb + SM_MK);

    int tid = threadIdx.x;
    int wid = tid >> 5, lane = tid & 31;
    int lq = lane >> 2, lr = lane & 3;
    int m0 = wid * 16;
    int q0 = blockIdx.x * 128;
    int h  = blockIdx.y;
    int b  = blockIdx.z;
    int bh = b * NH + h;

    uint32_t uKH = smem_u32p(Kh32), uKL = smem_u32p(Kl32);
    uint32_t uVH = smem_u32p(Vh32), uVL = smem_u32p(Vl32);

    {
        const uint32_t* qh = Qhi + ((size_t)bh * T + q0) * (DK / 2);
        const uint32_t* ql = Qlo + ((size_t)bh * T + q0) * (DK / 2);
        for (int idx = tid; idx < 128 * 32; idx += 256) {
            int r = idx >> 5, cc = idx & 31;
            Qh32[r * QSTR + cc] = qh[r * 32 + cc];
            Ql32[r * QSTR + cc] = ql[r * 32 + cc];
        }
    }

    float m_r0 = -1e30f, m_r1 = -1e30f, l_0 = 0.f, l_1 = 0.f;
    float oacc[8][4];
#pragma unroll
    for (int nt = 0; nt < 8; nt++)
#pragma unroll
        for (int i = 0; i < 4; i++) oacc[nt][i] = 0.f;

    const float scale = 0.125f;

    for (int k0 = 0; k0 < T; k0 += 128) {
        __syncthreads();
        {
            const uint32_t* kh = Khi + ((size_t)bh * T + k0) * (DK / 2);
            const uint32_t* kl = Klo + ((size_t)bh * T + k0) * (DK / 2);
            for (int idx = tid; idx < 128 * 16; idx += 256) {
                int r = idx >> 4, c2 = (idx & 15) * 2;
                uint32_t so = (uint32_t)(r * QSTR + c2) * 4;
                cp_async8(uKH + so, kh + r * 32 + c2);
                cp_async8(uKL + so, kl + r * 32 + c2);
            }
            const uint32_t* vh = Vhi + (size_t)bh * DK * (T / 2) + (k0 >> 1);
            const uint32_t* vl = Vlo + (size_t)bh * DK * (T / 2) + (k0 >> 1);
            for (int idx = tid; idx < 64 * 32; idx += 256) {
                int d = idx >> 5, j2 = (idx & 31) * 2;
                uint32_t so = (uint32_t)(d * VSTR + j2) * 4;
                cp_async8(uVH + so, vh + (size_t)d * (T / 2) + j2);
                cp_async8(uVL + so, vl + (size_t)d * (T / 2) + j2);
            }
            CP_COMMIT();
            if (tid < 128)
                Mk[tid] = mask[b * T + k0 + tid] ? 0.f : -1e30f;
            CP_WAIT0();
        }
        __syncthreads();

#pragma unroll
        for (int half = 0; half < 2; half++) {
            float sacc[8][4];
#pragma unroll
            for (int nt = 0; nt < 8; nt++)
#pragma unroll
                for (int i = 0; i < 4; i++) sacc[nt][i] = 0.f;

#pragma unroll
            for (int s = 0; s < 4; s++) {
                int ka = s * 8 + lr;
                int r = m0 + lq;
                uint32_t ah0 = Qh32[r * QSTR + ka],     ah1 = Qh32[(r + 8) * QSTR + ka];
                uint32_t ah2 = Qh32[r * QSTR + ka + 4], ah3 = Qh32[(r + 8) * QSTR + ka + 4];
                uint32_t al0 = Ql32[r * QSTR + ka],     al1 = Ql32[(r + 8) * QSTR + ka];
                uint32_t al2 = Ql32[r * QSTR + ka + 4], al3 = Ql32[(r + 8) * QSTR + ka + 4];
#pragma unroll
                for (int nt = 0; nt < 8; nt++) {
                    int rn = half * 64 + nt * 8 + lq;
                    uint32_t bh0 = Kh32[rn * QSTR + ka];
                    uint32_t bh1 = Kh32[rn * QSTR + ka + 4];
                    uint32_t bl0 = Kl32[rn * QSTR + ka];
                    uint32_t bl1 = Kl32[rn * QSTR + ka + 4];
                    MMA16816(sacc[nt], ah0, ah1, ah2, ah3, bh0, bh1);
                    MMA16816(sacc[nt], ah0, ah1, ah2, ah3, bl0, bl1);
                    MMA16816(sacc[nt], al0, al1, al2, al3, bh0, bh1);
                }
            }

            float mx0 = -1e30f, mx1 = -1e30f;
#pragma unroll
            for (int nt = 0; nt < 8; nt++) {
                int cc = half * 64 + nt * 8 + lr * 2;
                float k0m = Mk[cc], k1m = Mk[cc + 1];
                float s0 = sacc[nt][0] * scale + k0m;
                float s1 = sacc[nt][1] * scale + k1m;
                float s2 = sacc[nt][2] * scale + k0m;
                float s3 = sacc[nt][3] * scale + k1m;
                sacc[nt][0] = s0; sacc[nt][1] = s1; sacc[nt][2] = s2; sacc[nt][3] = s3;
                mx0 = fmaxf(mx0, fmaxf(s0, s1));
                mx1 = fmaxf(mx1, fmaxf(s2, s3));
            }
            mx0 = fmaxf(mx0, __shfl_xor_sync(0xffffffffu, mx0, 1));
            mx0 = fmaxf(mx0, __shfl_xor_sync(0xffffffffu, mx0, 2));
            mx1 = fmaxf(mx1, __shfl_xor_sync(0xffffffffu, mx1, 1));
            mx1 = fmaxf(mx1, __shfl_xor_sync(0xffffffffu, mx1, 2));
            float m_new0 = fmaxf(m_r0, mx0);
            float m_new1 = fmaxf(m_r1, mx1);

            float sum0 = 0.f, sum1 = 0.f;
#pragma unroll
            for (int nt = 0; nt < 8; nt++) {
                float p0 = __expf(sacc[nt][0] - m_new0);
                float p1 = __expf(sacc[nt][1] - m_new0);
                float p2 = __expf(sacc[nt][2] - m_new1);
                float p3 = __expf(sacc[nt][3] - m_new1);
                sacc[nt][0] = p0; sacc[nt][1] = p1; sacc[nt][2] = p2; sacc[nt][3] = p3;
                sum0 += p0 + p1;
                sum1 += p2 + p3;
            }
            sum0 += __shfl_xor_sync(0xffffffffu, sum0, 1);
            sum0 += __shfl_xor_sync(0xffffffffu, sum0, 2);
            sum1 += __shfl_xor_sync(0xffffffffu, sum1, 1);
            sum1 += __shfl_xor_sync(0xffffffffu, sum1, 2);

            float alpha0 = __expf(m_r0 - m_new0);
            float alpha1 = __expf(m_r1 - m_new1);
            l_0 = l_0 * alpha0 + sum0;
            l_1 = l_1 * alpha1 + sum1;
            m_r0 = m_new0;
            m_r1 = m_new1;
#pragma unroll
            for (int nt = 0; nt < 8; nt++) {
                oacc[nt][0] *= alpha0; oacc[nt][1] *= alpha0;
                oacc[nt][2] *= alpha1; oacc[nt][3] *= alpha1;
            }

#pragma unroll
            for (int kt = 0; kt < 4; kt++) {
                uint32_t pah[4], pal[4];
                split2(sacc[2 * kt][0],     sacc[2 * kt][1],     pah[0], pal[0]);
                split2(sacc[2 * kt][2],     sacc[2 * kt][3],     pah[1], pal[1]);
                split2(sacc[2 * kt + 1][0], sacc[2 * kt + 1][1], pah[2], pal[2]);
                split2(sacc[2 * kt + 1][2], sacc[2 * kt + 1][3], pah[3], pal[3]);
                int koff = half * 32 + kt * 8 + lr;
#pragma unroll
                for (int nt = 0; nt < 8; nt++) {
                    int rn = nt * 8 + lq;
                    uint32_t vh0 = Vh32[rn * VSTR + koff];
                    uint32_t vh1 = Vh32[rn * VSTR + koff + 4];
                    uint32_t vl0 = Vl32[rn * VSTR + koff];
                    uint32_t vl1 = Vl32[rn * VSTR + koff + 4];
                    MMA16816(oacc[nt], pah[0], pah[1], pah[2], pah[3], vh0, vh1);
                    MMA16816(oacc[nt], pah[0], pah[1], pah[2], pah[3], vl0, vl1);
                    MMA16816(oacc[nt], pal[0], pal[1], pal[2], pal[3], vh0, vh1);
                }
            }
        }
    }

    // ---- write split pairs directly (feeds final GEMM) ----
    float inv0 = 1.f / l_0, inv1 = 1.f / l_1;
    int row0 = q0 + m0 + lq;
#pragma unroll
    for (int nt = 0; nt < 8; nt++) {
        int dp = (h * DK + nt * 8 + lr * 2) >> 1;
        uint32_t hh, ll;
        split2(oacc[nt][0] * inv0, oacc[nt][1] * inv0, hh, ll);
        size_t o0 = (size_t)(b * T + row0) * (DM / 2) + dp;
        Ohi[o0] = hh;
        Olo[o0] = ll;
        split2(oacc[nt][2] * inv1, oacc[nt][3] * inv1, hh, ll);
        size_t o1 = (size_t)(b * T + row0 + 8) * (DM / 2) + dp;
        Ohi[o1] = hh;
        Olo[o1] = ll;
    }
}

// ---------------------------------------------------------------------------
extern "C" void kernel_launch(void* const* d_in, const int* in_sizes, int n_in,
                              void* d_out, int out_size)
{
    const float* q   = (const float*)d_in[0];
    const float* k   = (const float*)d_in[1];
    const float* v   = (const float*)d_in[2];
    const int*   msk = (const int*)  d_in[3];
    const float* Wq  = (const float*)d_in[4];
    const float* bq  = (const float*)d_in[5];
    const float* Wk  = (const float*)d_in[6];
    const float* bk  = (const float*)d_in[7];
    const float* Wv  = (const float*)d_in[8];
    const float* bv  = (const float*)d_in[9];
    const float* Wo  = (const float*)d_in[10];
    const float* bo  = (const float*)d_in[11];
    float* out = (float*)d_out;

    uint32_t *Qhi, *Qlo, *Khi, *Klo, *Vhi, *Vlo, *Ahi, *Alo, *Whi, *Wlo;
    cudaGetSymbolAddress((void**)&Qhi, g_Qhi);
    cudaGetSymbolAddress((void**)&Qlo, g_Qlo);
    cudaGetSymbolAddress((void**)&Khi, g_Khi);
    cudaGetSymbolAddress((void**)&Klo, g_Klo);
    cudaGetSymbolAddress((void**)&Vhi, g_Vhi);
    cudaGetSymbolAddress((void**)&Vlo, g_Vlo);
    cudaGetSymbolAddress((void**)&Ahi, g_Ahi);
    cudaGetSymbolAddress((void**)&Alo, g_Alo);
    cudaGetSymbolAddress((void**)&Whi, g_Whi);
    cudaGetSymbolAddress((void**)&Wlo, g_Wlo);

    cudaFuncSetAttribute(gemm_mma,
                         cudaFuncAttributeMaxDynamicSharedMemorySize, GEMM_SMEM);
    cudaFuncSetAttribute(attn_mma,
                         cudaFuncAttributeMaxDynamicSharedMemorySize, ATTN_SMEM);

    dim3 gg(DM / 128, NT / 128);   // (8, 32)
    dim3 gw(DM / 32, DM / 64);     // (32, 16)
    int ga_blocks = NT * (DM / 2) / 256;   // 8192

    split_w_kernel<<<gw, 256>>>(Wq, Whi, Wlo);
    split_a_kernel<<<ga_blocks, 256>>>(q, Ahi, Alo);
    gemm_mma<<<gg, 256, GEMM_SMEM>>>(Ahi, Alo, Whi, Wlo, bq, nullptr, Qhi, Qlo, 1);

    split_w_kernel<<<gw, 256>>>(Wk, Whi, Wlo);
    split_a_kernel<<<ga_blocks, 256>>>(k, Ahi, Alo);
    gemm_mma<<<gg, 256, GEMM_SMEM>>>(Ahi, Alo, Whi, Wlo, bk, nullptr, Khi, Klo, 1);

    split_w_kernel<<<gw, 256>>>(Wv, Whi, Wlo);
    split_a_kernel<<<ga_blocks, 256>>>(v, Ahi, Alo);
    gemm_mma<<<gg, 256, GEMM_SMEM>>>(Ahi, Alo, Whi, Wlo, bv, nullptr, Vhi, Vlo, 2);

    dim3 gat(T / 128, NH, NB);     // (16, 16, 2)
    attn_mma<<<gat, 256, ATTN_SMEM>>>(Qhi, Qlo, Khi, Klo, Vhi, Vlo, msk, Ahi, Alo);

    split_w_kernel<<<gw, 256>>>(Wo, Whi, Wlo);
    gemm_mma<<<gg, 256, GEMM_SMEM>>>(Ahi, Alo, Whi, Wlo, bo, out, nullptr, nullptr, 0);
}